// round 3
// baseline (speedup 1.0000x reference)
#include <cuda_runtime.h>
#include <math.h>

#define NN 100
#define CC 32
#define HH 512
#define TT 64
#define BB 16
#define EE 2000
#define HZ 10
#define NC 3200    // NN*CC
#define G4 2048    // 4*HH
#define TB 1024    // TT*BB

// ------------------------- device scratch -------------------------
__device__ float g_norm[EE];
__device__ float g_Xin[TB * NC];             // (t*B+b, NC)
__device__ float g_G0[TB * G4];              // L0 input projections + biases
__device__ float g_G1[TB * G4];              // L1 input projections + biases
__device__ float g_hs0[(TT + 1) * BB * HH];  // slot 0 = zeros (initial h)
__device__ float g_hs1[(TT + 1) * BB * HH];
__device__ float g_c0[BB * HH];
__device__ float g_c1l[BB * HH];
__device__ float g_dh1[2][BB * HH];
__device__ float g_dh2[2][BB * HH];
__device__ float g_dc1[BB * HH];
__device__ float g_dc2[BB * HH];
__device__ float g_dxin[BB * NC];

__device__ __forceinline__ float geluf(float x) {
    return 0.5f * x * (1.0f + erff(x * 0.70710678118654752f));
}
__device__ __forceinline__ float sigmf(float x) { return 1.0f / (1.0f + expf(-x)); }

// ------------------------- init / prep -------------------------
__global__ void k_zero() {
    int i = blockIdx.x * blockDim.x + threadIdx.x;
    if (i < BB * HH) { g_c0[i] = 0.f; g_c1l[i] = 0.f; }
}

__global__ void k_prep(const int* __restrict__ ei, const float* __restrict__ ew) {
    __shared__ float sdeg[NN];
    __shared__ float sdinv[NN];
    int tid = threadIdx.x;
    for (int n = tid; n < NN; n += blockDim.x) sdeg[n] = 0.f;
    __syncthreads();
    for (int e = tid; e < EE; e += blockDim.x) atomicAdd(&sdeg[ei[EE + e]], ew[e]);
    __syncthreads();
    for (int n = tid; n < NN; n += blockDim.x) {
        float d = sdeg[n];
        sdinv[n] = (d > 0.f) ? rsqrtf(fmaxf(d, 1e-12f)) : 0.f;
    }
    __syncthreads();
    for (int e = tid; e < EE; e += blockDim.x)
        g_norm[e] = sdinv[ei[e]] * ew[e] * sdinv[ei[EE + e]];
}

// ------------------------- temporal ARMA + embed -------------------------
// replica p = tg*16+bg; node ids base..base+99; x[node j] = window_flat[j]
__global__ void k_tg(const float* __restrict__ win, const int* __restrict__ ei,
                     const float* __restrict__ tw, const float* __restrict__ tv,
                     const float* __restrict__ tb, const float* __restrict__ emb) {
    __shared__ float s[NN];
    int p = blockIdx.x;
    int base = (p >> 4) * (BB * NN) + (p & 15) * NN;
    int tid = threadIdx.x;
    for (int n = tid; n < NN; n += blockDim.x) s[n] = 0.f;
    __syncthreads();
    for (int e = tid; e < EE; e += blockDim.x)
        atomicAdd(&s[ei[EE + e]], g_norm[e] * win[base + ei[e]]);
    __syncthreads();
    for (int idx = tid; idx < NC; idx += blockDim.x) {
        int n = idx >> 5, c = idx & 31;
        float x = win[base + n];
        float val = geluf(s[n] * tw[c] + x * tv[c] + tb[c]);
        int j = base + n;                  // j == (b2*NN+n2)*TT + t2
        int t2 = j & (TT - 1);
        int rest = j >> 6;
        int n2 = rest % NN, b2 = rest / NN;
        g_Xin[(size_t)(t2 * BB + b2) * NC + n2 * CC + c] = val + emb[n2 * CC + c];
    }
}

// ------------------------- NT SGEMM (M=1024, N=2048) -------------------------
// sel 0: A=g_Xin K=3200 -> g_G0 ; sel 1: A=g_hs0+B*H K=512 -> g_G1
__global__ void k_gemm_nt(int sel, const float* __restrict__ W,
                          const float* __restrict__ b1, const float* __restrict__ b2) {
    const float* A;
    float* Cc;
    int K;
    if (sel == 0) { A = g_Xin; Cc = g_G0; K = NC; }
    else          { A = g_hs0 + BB * HH; Cc = g_G1; K = HH; }

    __shared__ __align__(16) float As[16][128];
    __shared__ __align__(16) float Bs[16][128];
    int tid = threadIdx.x;
    int m0 = blockIdx.y * 128, n0 = blockIdx.x * 128;
    int tm = tid >> 4, tn = tid & 15;
    int li = tid >> 2, lj = (tid & 3) << 2;

    float acc[8][8];
#pragma unroll
    for (int i = 0; i < 8; i++)
#pragma unroll
        for (int j = 0; j < 8; j++) acc[i][j] = 0.f;

    for (int k0 = 0; k0 < K; k0 += 16) {
        float4 a0 = *reinterpret_cast<const float4*>(A + (size_t)(m0 + li) * K + k0 + lj);
        float4 a1 = *reinterpret_cast<const float4*>(A + (size_t)(m0 + li + 64) * K + k0 + lj);
        float4 w0 = *reinterpret_cast<const float4*>(W + (size_t)(n0 + li) * K + k0 + lj);
        float4 w1 = *reinterpret_cast<const float4*>(W + (size_t)(n0 + li + 64) * K + k0 + lj);
        __syncthreads();
        As[lj + 0][li] = a0.x; As[lj + 1][li] = a0.y; As[lj + 2][li] = a0.z; As[lj + 3][li] = a0.w;
        As[lj + 0][li + 64] = a1.x; As[lj + 1][li + 64] = a1.y; As[lj + 2][li + 64] = a1.z; As[lj + 3][li + 64] = a1.w;
        Bs[lj + 0][li] = w0.x; Bs[lj + 1][li] = w0.y; Bs[lj + 2][li] = w0.z; Bs[lj + 3][li] = w0.w;
        Bs[lj + 0][li + 64] = w1.x; Bs[lj + 1][li + 64] = w1.y; Bs[lj + 2][li + 64] = w1.z; Bs[lj + 3][li + 64] = w1.w;
        __syncthreads();
#pragma unroll
        for (int kk = 0; kk < 16; kk++) {
            float ra[8], rb[8];
            *reinterpret_cast<float4*>(&ra[0]) = *reinterpret_cast<float4*>(&As[kk][tm * 8]);
            *reinterpret_cast<float4*>(&ra[4]) = *reinterpret_cast<float4*>(&As[kk][tm * 8 + 4]);
            *reinterpret_cast<float4*>(&rb[0]) = *reinterpret_cast<float4*>(&Bs[kk][tn * 8]);
            *reinterpret_cast<float4*>(&rb[4]) = *reinterpret_cast<float4*>(&Bs[kk][tn * 8 + 4]);
#pragma unroll
            for (int i = 0; i < 8; i++)
#pragma unroll
                for (int j = 0; j < 8; j++) acc[i][j] += ra[i] * rb[j];
        }
    }

    float bias[8];
#pragma unroll
    for (int j = 0; j < 8; j++) bias[j] = b1[n0 + tn * 8 + j] + b2[n0 + tn * 8 + j];
#pragma unroll
    for (int i = 0; i < 8; i++) {
        float* cp = Cc + (size_t)(m0 + tm * 8 + i) * G4 + n0 + tn * 8;
#pragma unroll
        for (int j = 0; j < 8; j++) cp[j] = acc[i][j] + bias[j];
    }
}

// ------------------------- LSTM recurrence step (input proj precomputed) ----
// 128 blocks x 256 threads; block owns 4 hidden units across all 4 gates
__global__ void k_step_pre(int layer, int t, const float* __restrict__ Whh) {
    const float* G = (layer == 0 ? g_G0 : g_G1) + (size_t)t * BB * G4;
    float* hs = (layer == 0 ? g_hs0 : g_hs1);
    const float* h_in = hs + (size_t)t * BB * HH;
    float* h_out = hs + (size_t)(t + 1) * BB * HH;
    float* c_st = (layer == 0 ? g_c0 : g_c1l);

    __shared__ float sh[HH * BB];    // [k][b]
    __shared__ float sg[16 * BB];
    int tid = threadIdx.x;
    for (int i = tid; i < HH * BB; i += 256) {
        int b = i >> 9, k = i & (HH - 1);
        sh[k * BB + b] = h_in[i];
    }
    __syncthreads();

    int rowid = tid >> 4, bb = tid & 15;
    int gate = rowid >> 2, jj = rowid & 3;
    int row = gate * HH + blockIdx.x * 4 + jj;
    const float* w = Whh + (size_t)row * HH;
    float acc = 0.f;
#pragma unroll 4
    for (int k = 0; k < HH; k += 4) {
        float4 wv = *reinterpret_cast<const float4*>(w + k);
        acc += wv.x * sh[(k + 0) * BB + bb] + wv.y * sh[(k + 1) * BB + bb]
             + wv.z * sh[(k + 2) * BB + bb] + wv.w * sh[(k + 3) * BB + bb];
    }
    sg[rowid * BB + bb] = acc + G[bb * G4 + row];
    __syncthreads();

    if (tid < 64) {
        int jq = tid >> 4, b = tid & 15;
        float iv = sigmf(sg[(0 + jq) * BB + b]);
        float fv = sigmf(sg[(4 + jq) * BB + b]);
        float gv = tanhf(sg[(8 + jq) * BB + b]);
        float ov = sigmf(sg[(12 + jq) * BB + b]);
        int idx = b * HH + blockIdx.x * 4 + jq;
        float cn = fv * c_st[idx] + iv * gv;
        c_st[idx] = cn;
        h_out[idx] = ov * tanhf(cn);
    }
}

// ------------------------- decoder state seed -------------------------
__global__ void k_copyfin() {
    int i = blockIdx.x * blockDim.x + threadIdx.x;
    if (i < BB * HH) {
        float v0 = g_hs0[(size_t)TT * BB * HH + i];
        g_dh1[0][i] = v0; g_dc1[i] = v0;
        float v1 = g_hs1[(size_t)TT * BB * HH + i];
        g_dh2[0][i] = v1; g_dc2[i] = v1;
    }
}

// ------------------------- decoder: pred + ARMA + xin -------------------------
__global__ void k_dec_a(int parity, const float* __restrict__ Wp,
                        const float* __restrict__ bp, const int* __restrict__ ei,
                        const float* __restrict__ gw, const float* __restrict__ gv,
                        const float* __restrict__ gb, const float* __restrict__ emb,
                        float* __restrict__ out, int hstep) {
    const float* h2 = g_dh2[parity];
    __shared__ float sh2[HH];
    __shared__ float spred[NN];
    __shared__ float ss[NN];
    int b = blockIdx.x, tid = threadIdx.x;
    for (int i = tid; i < HH; i += 128) sh2[i] = h2[b * HH + i];
    for (int i = tid; i < NN; i += 128) ss[i] = 0.f;
    __syncthreads();
    for (int n = tid; n < NN; n += 128) {
        const float* wr = Wp + (size_t)n * HH;
        float d = bp[n];
#pragma unroll 4
        for (int k = 0; k < HH; k += 4) {
            float4 wv = *reinterpret_cast<const float4*>(wr + k);
            d += wv.x * sh2[k] + wv.y * sh2[k + 1] + wv.z * sh2[k + 2] + wv.w * sh2[k + 3];
        }
        spred[n] = d;
        out[(b * NN + n) * HZ + hstep] = d;
    }
    __syncthreads();
    for (int e = tid; e < EE; e += 128)
        atomicAdd(&ss[ei[EE + e]], g_norm[e] * spred[ei[e]]);
    __syncthreads();
    for (int idx = tid; idx < NC; idx += 128) {
        int n = idx >> 5, c = idx & 31;
        float val = geluf(ss[n] * gw[c] + spred[n] * gv[c] + gb[c]);
        g_dxin[(size_t)b * NC + idx] = val + emb[idx];
    }
}

// ------------------------- decoder full LSTM cell step -------------------------
// which 1: x=g_dxin (K=3200), states dh1/dc1 ; which 2: x=new h1 (K=512), dh2/dc2
__global__ void k_step_full(int which, int parity, const float* __restrict__ Wih,
                            const float* __restrict__ Whh,
                            const float* __restrict__ bih,
                            const float* __restrict__ bhh) {
    const float* x;
    int Kx;
    const float* h_in;
    float* h_out;
    float* c_st;
    if (which == 1) {
        x = g_dxin; Kx = NC;
        h_in = g_dh1[parity]; h_out = g_dh1[parity ^ 1]; c_st = g_dc1;
    } else {
        x = g_dh1[parity ^ 1]; Kx = HH;
        h_in = g_dh2[parity]; h_out = g_dh2[parity ^ 1]; c_st = g_dc2;
    }

    __shared__ float sh[HH * BB];
    __shared__ float sg[16 * BB];
    int tid = threadIdx.x;
    int rowid = tid >> 4, bb = tid & 15;
    int gate = rowid >> 2, jj = rowid & 3;
    int row = gate * HH + blockIdx.x * 4 + jj;
    float acc = 0.f;

    for (int k0 = 0; k0 < Kx; k0 += HH) {
        int len = min(HH, Kx - k0);
        __syncthreads();
        for (int i = tid; i < len * BB; i += 256) {
            int kk = i >> 4, b = i & 15;
            sh[i] = x[(size_t)b * Kx + k0 + kk];
        }
        __syncthreads();
        const float* w = Wih + (size_t)row * Kx + k0;
#pragma unroll 4
        for (int k = 0; k < len; k += 4) {
            float4 wv = *reinterpret_cast<const float4*>(w + k);
            acc += wv.x * sh[(k + 0) * BB + bb] + wv.y * sh[(k + 1) * BB + bb]
                 + wv.z * sh[(k + 2) * BB + bb] + wv.w * sh[(k + 3) * BB + bb];
        }
    }

    __syncthreads();
    for (int i = tid; i < HH * BB; i += 256) {
        int b = i >> 9, k = i & (HH - 1);
        sh[k * BB + b] = h_in[i];
    }
    __syncthreads();
    const float* w2 = Whh + (size_t)row * HH;
#pragma unroll 4
    for (int k = 0; k < HH; k += 4) {
        float4 wv = *reinterpret_cast<const float4*>(w2 + k);
        acc += wv.x * sh[(k + 0) * BB + bb] + wv.y * sh[(k + 1) * BB + bb]
             + wv.z * sh[(k + 2) * BB + bb] + wv.w * sh[(k + 3) * BB + bb];
    }
    sg[rowid * BB + bb] = acc + bih[row] + bhh[row];
    __syncthreads();

    if (tid < 64) {
        int jq = tid >> 4, b = tid & 15;
        float iv = sigmf(sg[(0 + jq) * BB + b]);
        float fv = sigmf(sg[(4 + jq) * BB + b]);
        float gv = tanhf(sg[(8 + jq) * BB + b]);
        float ov = sigmf(sg[(12 + jq) * BB + b]);
        int idx = b * HH + blockIdx.x * 4 + jq;
        float cn = fv * c_st[idx] + iv * gv;
        c_st[idx] = cn;
        h_out[idx] = ov * tanhf(cn);
    }
}

// ------------------------- launch -------------------------
extern "C" void kernel_launch(void* const* d_in, const int* in_sizes, int n_in,
                              void* d_out, int out_size) {
    const float* window = (const float*)d_in[0];
    const int*   ei     = (const int*)d_in[1];
    const float* ew     = (const float*)d_in[2];
    const float* emb    = (const float*)d_in[3];
    const float* tg_w   = (const float*)d_in[4];
    const float* tg_v   = (const float*)d_in[5];
    const float* tg_b   = (const float*)d_in[6];
    const float* gnn_w  = (const float*)d_in[7];
    const float* gnn_v  = (const float*)d_in[8];
    const float* gnn_b  = (const float*)d_in[9];
    const float* Wih0   = (const float*)d_in[10];
    const float* Whh0   = (const float*)d_in[11];
    const float* bih0   = (const float*)d_in[12];
    const float* bhh0   = (const float*)d_in[13];
    const float* Wih1   = (const float*)d_in[14];
    const float* Whh1   = (const float*)d_in[15];
    const float* bih1   = (const float*)d_in[16];
    const float* bhh1   = (const float*)d_in[17];
    const float* c1Wih  = (const float*)d_in[18];
    const float* c1Whh  = (const float*)d_in[19];
    const float* c1bih  = (const float*)d_in[20];
    const float* c1bhh  = (const float*)d_in[21];
    const float* c2Wih  = (const float*)d_in[22];
    const float* c2Whh  = (const float*)d_in[23];
    const float* c2bih  = (const float*)d_in[24];
    const float* c2bhh  = (const float*)d_in[25];
    const float* Wp     = (const float*)d_in[26];
    const float* bp     = (const float*)d_in[27];
    float* out = (float*)d_out;

    k_zero<<<32, 256>>>();
    k_prep<<<1, 256>>>(ei, ew);
    k_tg<<<TB, 256>>>(window, ei, tg_w, tg_v, tg_b, emb);

    dim3 gg(G4 / 128, TB / 128);
    k_gemm_nt<<<gg, 256>>>(0, Wih0, bih0, bhh0);
    for (int t = 0; t < TT; t++) k_step_pre<<<128, 256>>>(0, t, Whh0);
    k_gemm_nt<<<gg, 256>>>(1, Wih1, bih1, bhh1);
    for (int t = 0; t < TT; t++) k_step_pre<<<128, 256>>>(1, t, Whh1);

    k_copyfin<<<32, 256>>>();
    for (int h = 0; h < HZ; h++) {
        int par = h & 1;
        k_dec_a<<<BB, 128>>>(par, Wp, bp, ei, gnn_w, gnn_v, gnn_b, emb, out, h);
        k_step_full<<<128, 256>>>(1, par, c1Wih, c1Whh, c1bih, c1bhh);
        k_step_full<<<128, 256>>>(2, par, c2Wih, c2Whh, c2bih, c2bhh);
    }
    (void)in_sizes; (void)n_in; (void)out_size;
}

// round 4
// speedup vs baseline: 1.8061x; 1.8061x over previous
#include <cuda_runtime.h>
#include <math.h>

#define NN 100
#define CC 32
#define HH 512
#define TT 64
#define BB 16
#define EE 2000
#define HZ 10
#define NC 3200    // NN*CC
#define G4 2048    // 4*HH
#define TB 1024    // TT*BB
#define NBLK 128   // persistent grid size

// ------------------------- device scratch -------------------------
__device__ float g_norm[EE];
__device__ float g_Xin[TB * NC];
__device__ float g_G0[TB * G4];
__device__ float g_G1[TB * G4];
__device__ float g_hs0[(TT + 1) * BB * HH];   // slot 0 never written => zeros
__device__ float g_hs1[(TT + 1) * BB * HH];
__device__ float g_c0[BB * HH];
__device__ float g_c1l[BB * HH];
__device__ float g_dh1s[HZ + 1][BB * HH];
__device__ float g_dh2s[HZ + 1][BB * HH];
__device__ float g_dc1[BB * HH];
__device__ float g_dc2[BB * HH];
__device__ float g_dxins[HZ][BB * NC];
__device__ unsigned g_barctr[3];

__device__ __forceinline__ float geluf(float x) {
    return 0.5f * x * (1.0f + erff(x * 0.70710678118654752f));
}
__device__ __forceinline__ float sigmf(float x) { return 1.0f / (1.0f + expf(-x)); }

// grid barrier: all NBLK blocks co-resident (grid <= #SMs)
__device__ __forceinline__ void gbar(unsigned* ctr, unsigned& tgt) {
    __threadfence();
    __syncthreads();
    if (threadIdx.x == 0) {
        atomicAdd(ctr, 1u);
        while (*(volatile unsigned*)ctr < tgt) { }
    }
    __syncthreads();
    tgt += NBLK;
}

// ------------------------- init / prep -------------------------
__global__ void k_zero() {
    int i = blockIdx.x * blockDim.x + threadIdx.x;
    if (i < BB * HH) { g_c0[i] = 0.f; g_c1l[i] = 0.f; }
    if (i < 3) g_barctr[i] = 0u;
}

__global__ void k_prep(const int* __restrict__ ei, const float* __restrict__ ew) {
    __shared__ float sdeg[NN];
    __shared__ float sdinv[NN];
    int tid = threadIdx.x;
    for (int n = tid; n < NN; n += blockDim.x) sdeg[n] = 0.f;
    __syncthreads();
    for (int e = tid; e < EE; e += blockDim.x) atomicAdd(&sdeg[ei[EE + e]], ew[e]);
    __syncthreads();
    for (int n = tid; n < NN; n += blockDim.x) {
        float d = sdeg[n];
        sdinv[n] = (d > 0.f) ? rsqrtf(fmaxf(d, 1e-12f)) : 0.f;
    }
    __syncthreads();
    for (int e = tid; e < EE; e += blockDim.x)
        g_norm[e] = sdinv[ei[e]] * ew[e] * sdinv[ei[EE + e]];
}

// ------------------------- temporal ARMA + embed -------------------------
__global__ void k_tg(const float* __restrict__ win, const int* __restrict__ ei,
                     const float* __restrict__ tw, const float* __restrict__ tv,
                     const float* __restrict__ tb, const float* __restrict__ emb) {
    __shared__ float s[NN];
    int p = blockIdx.x;
    int base = (p >> 4) * (BB * NN) + (p & 15) * NN;
    int tid = threadIdx.x;
    for (int n = tid; n < NN; n += blockDim.x) s[n] = 0.f;
    __syncthreads();
    for (int e = tid; e < EE; e += blockDim.x)
        atomicAdd(&s[ei[EE + e]], g_norm[e] * win[base + ei[e]]);
    __syncthreads();
    for (int idx = tid; idx < NC; idx += blockDim.x) {
        int n = idx >> 5, c = idx & 31;
        float x = win[base + n];
        float val = geluf(s[n] * tw[c] + x * tv[c] + tb[c]);
        int j = base + n;
        int t2 = j & (TT - 1);
        int rest = j >> 6;
        int n2 = rest % NN, b2 = rest / NN;
        g_Xin[(size_t)(t2 * BB + b2) * NC + n2 * CC + c] = val + emb[n2 * CC + c];
    }
}

// ------------------------- NT SGEMM (M=1024, N=2048) -------------------------
__global__ void k_gemm_nt(int sel, const float* __restrict__ W,
                          const float* __restrict__ b1, const float* __restrict__ b2) {
    const float* A;
    float* Cc;
    int K;
    if (sel == 0) { A = g_Xin; Cc = g_G0; K = NC; }
    else          { A = g_hs0 + BB * HH; Cc = g_G1; K = HH; }

    __shared__ __align__(16) float As[16][128];
    __shared__ __align__(16) float Bs[16][128];
    int tid = threadIdx.x;
    int m0 = blockIdx.y * 128, n0 = blockIdx.x * 128;
    int tm = tid >> 4, tn = tid & 15;
    int li = tid >> 2, lj = (tid & 3) << 2;

    float acc[8][8];
#pragma unroll
    for (int i = 0; i < 8; i++)
#pragma unroll
        for (int j = 0; j < 8; j++) acc[i][j] = 0.f;

    for (int k0 = 0; k0 < K; k0 += 16) {
        float4 a0 = *reinterpret_cast<const float4*>(A + (size_t)(m0 + li) * K + k0 + lj);
        float4 a1 = *reinterpret_cast<const float4*>(A + (size_t)(m0 + li + 64) * K + k0 + lj);
        float4 w0 = *reinterpret_cast<const float4*>(W + (size_t)(n0 + li) * K + k0 + lj);
        float4 w1 = *reinterpret_cast<const float4*>(W + (size_t)(n0 + li + 64) * K + k0 + lj);
        __syncthreads();
        As[lj + 0][li] = a0.x; As[lj + 1][li] = a0.y; As[lj + 2][li] = a0.z; As[lj + 3][li] = a0.w;
        As[lj + 0][li + 64] = a1.x; As[lj + 1][li + 64] = a1.y; As[lj + 2][li + 64] = a1.z; As[lj + 3][li + 64] = a1.w;
        Bs[lj + 0][li] = w0.x; Bs[lj + 1][li] = w0.y; Bs[lj + 2][li] = w0.z; Bs[lj + 3][li] = w0.w;
        Bs[lj + 0][li + 64] = w1.x; Bs[lj + 1][li + 64] = w1.y; Bs[lj + 2][li + 64] = w1.z; Bs[lj + 3][li + 64] = w1.w;
        __syncthreads();
#pragma unroll
        for (int kk = 0; kk < 16; kk++) {
            float ra[8], rb[8];
            *reinterpret_cast<float4*>(&ra[0]) = *reinterpret_cast<float4*>(&As[kk][tm * 8]);
            *reinterpret_cast<float4*>(&ra[4]) = *reinterpret_cast<float4*>(&As[kk][tm * 8 + 4]);
            *reinterpret_cast<float4*>(&rb[0]) = *reinterpret_cast<float4*>(&Bs[kk][tn * 8]);
            *reinterpret_cast<float4*>(&rb[4]) = *reinterpret_cast<float4*>(&Bs[kk][tn * 8 + 4]);
#pragma unroll
            for (int i = 0; i < 8; i++)
#pragma unroll
                for (int j = 0; j < 8; j++) acc[i][j] += ra[i] * rb[j];
        }
    }

    float bias[8];
#pragma unroll
    for (int j = 0; j < 8; j++) bias[j] = b1[n0 + tn * 8 + j] + b2[n0 + tn * 8 + j];
#pragma unroll
    for (int i = 0; i < 8; i++) {
        float* cp = Cc + (size_t)(m0 + tm * 8 + i) * G4 + n0 + tn * 8;
#pragma unroll
        for (int j = 0; j < 8; j++) cp[j] = acc[i][j] + bias[j];
    }
}

// ------------------------- persistent recurrence (one layer, 64 steps) ------
// dyn smem: swhh[16*512] | sh[16*516] | sg[256]
extern __shared__ float dynsm[];

__global__ void __launch_bounds__(256) k_rec(int layer, const float* __restrict__ Whh) {
    float* swhh = dynsm;
    float* sh = dynsm + 16 * 512;
    float* sg = dynsm + 16 * 512 + 16 * 516;
    const float* Gall = (layer == 0) ? g_G0 : g_G1;
    float* hs = (layer == 0) ? g_hs0 : g_hs1;
    float* c_st = (layer == 0) ? g_c0 : g_c1l;
    unsigned* ctr = &g_barctr[layer];

    int tid = threadIdx.x;
    int rowid = tid >> 4, bb = tid & 15;
    int bq = tid >> 4, q = tid & 15;
    int row = (rowid >> 2) * HH + blockIdx.x * 4 + (rowid & 3);

    // cache the block's 16 Whh rows in smem (once for all 64 steps)
    for (int i = tid; i < 16 * 128; i += 256) {
        int r = i >> 7, k4 = (i & 127) << 2;
        int grow = (r >> 2) * HH + blockIdx.x * 4 + (r & 3);
        *reinterpret_cast<float4*>(swhh + r * 512 + k4) =
            *reinterpret_cast<const float4*>(Whh + (size_t)grow * HH + k4);
    }

    unsigned tgt = NBLK;
    for (int t = 0; t < TT; t++) {
        const float* h_in = hs + (size_t)t * BB * HH;
        __syncthreads();
#pragma unroll
        for (int m = 0; m < 8; m++) {
            float4 v = *reinterpret_cast<const float4*>(h_in + bq * HH + m * 64 + q * 4);
            *reinterpret_cast<float4*>(sh + bq * 516 + m * 64 + q * 4) = v;
        }
        __syncthreads();
        const float* w = swhh + rowid * 512;
        const float* hr = sh + bb * 516;
        float a0 = 0.f, a1 = 0.f, a2 = 0.f, a3 = 0.f;
#pragma unroll 16
        for (int k = 0; k < HH; k += 4) {
            float4 wv = *reinterpret_cast<const float4*>(w + k);
            float4 hv = *reinterpret_cast<const float4*>(hr + k);
            a0 += wv.x * hv.x; a1 += wv.y * hv.y; a2 += wv.z * hv.z; a3 += wv.w * hv.w;
        }
        sg[rowid * 16 + bb] = (a0 + a1) + (a2 + a3) +
                              Gall[(size_t)t * BB * G4 + bb * G4 + row];
        __syncthreads();
        if (tid < 64) {
            int jq = tid >> 4, b = tid & 15;
            float iv = sigmf(sg[jq * 16 + b]);
            float fv = sigmf(sg[(4 + jq) * 16 + b]);
            float gv = tanhf(sg[(8 + jq) * 16 + b]);
            float ov = sigmf(sg[(12 + jq) * 16 + b]);
            int idx = b * HH + blockIdx.x * 4 + jq;
            float cn = fv * c_st[idx] + iv * gv;
            c_st[idx] = cn;
            hs[(size_t)(t + 1) * BB * HH + idx] = ov * tanhf(cn);
        }
        if (t < TT - 1) gbar(ctr, tgt);
    }
}

// ------------------------- decoder state seed -------------------------
__global__ void k_copyfin() {
    int i = blockIdx.x * blockDim.x + threadIdx.x;
    if (i < BB * HH) {
        float v0 = g_hs0[(size_t)TT * BB * HH + i];
        g_dh1s[0][i] = v0; g_dc1[i] = v0;
        float v1 = g_hs1[(size_t)TT * BB * HH + i];
        g_dh2s[0][i] = v1; g_dc2[i] = v1;
    }
}

// ------------------------- decoder LSTM cell (device) -------------------------
__device__ __forceinline__ void cellstep(
    const float* __restrict__ x, int Kx,
    const float* __restrict__ h_in, float* __restrict__ h_out,
    float* __restrict__ c_st,
    const float* __restrict__ Wih, const float* __restrict__ Whh,
    const float* __restrict__ bih, const float* __restrict__ bhh,
    float* s_x, float* s_g)
{
    int tid = threadIdx.x;
    int rowid = tid >> 4, bb = tid & 15;
    int bq = tid >> 4, q = tid & 15;
    int row = (rowid >> 2) * HH + blockIdx.x * 4 + (rowid & 3);
    float a0 = 0.f, a1 = 0.f, a2 = 0.f, a3 = 0.f;

    for (int k0 = 0; k0 < Kx; k0 += 512) {
        int len = min(512, Kx - k0);
        __syncthreads();
        for (int m = 0; m * 64 < len; m++) {
            float4 v = *reinterpret_cast<const float4*>(x + (size_t)bq * Kx + k0 + m * 64 + q * 4);
            *reinterpret_cast<float4*>(s_x + bq * 516 + m * 64 + q * 4) = v;
        }
        __syncthreads();
        const float* w = Wih + (size_t)row * Kx + k0;
        const float* hr = s_x + bb * 516;
#pragma unroll 8
        for (int k = 0; k < len; k += 4) {
            float4 wv = *reinterpret_cast<const float4*>(w + k);
            float4 hv = *reinterpret_cast<const float4*>(hr + k);
            a0 += wv.x * hv.x; a1 += wv.y * hv.y; a2 += wv.z * hv.z; a3 += wv.w * hv.w;
        }
    }

    __syncthreads();
#pragma unroll
    for (int m = 0; m < 8; m++) {
        float4 v = *reinterpret_cast<const float4*>(h_in + bq * HH + m * 64 + q * 4);
        *reinterpret_cast<float4*>(s_x + bq * 516 + m * 64 + q * 4) = v;
    }
    __syncthreads();
    {
        const float* w = Whh + (size_t)row * HH;
        const float* hr = s_x + bb * 516;
#pragma unroll 8
        for (int k = 0; k < HH; k += 4) {
            float4 wv = *reinterpret_cast<const float4*>(w + k);
            float4 hv = *reinterpret_cast<const float4*>(hr + k);
            a0 += wv.x * hv.x; a1 += wv.y * hv.y; a2 += wv.z * hv.z; a3 += wv.w * hv.w;
        }
    }
    s_g[rowid * 16 + bb] = (a0 + a1) + (a2 + a3) + bih[row] + bhh[row];
    __syncthreads();
    if (tid < 64) {
        int jq = tid >> 4, b = tid & 15;
        float iv = sigmf(s_g[jq * 16 + b]);
        float fv = sigmf(s_g[(4 + jq) * 16 + b]);
        float gv = tanhf(s_g[(8 + jq) * 16 + b]);
        float ov = sigmf(s_g[(12 + jq) * 16 + b]);
        int idx = b * HH + blockIdx.x * 4 + jq;
        float cn = fv * c_st[idx] + iv * gv;
        c_st[idx] = cn;
        h_out[idx] = ov * tanhf(cn);
    }
}

// ------------------------- persistent decoder (all 10 horizon steps) --------
__global__ void __launch_bounds__(256) k_dec(
    const float* __restrict__ Wp, const float* __restrict__ bp,
    const int* __restrict__ ei,
    const float* __restrict__ gw, const float* __restrict__ gv,
    const float* __restrict__ gb, const float* __restrict__ emb,
    const float* __restrict__ c1Wih, const float* __restrict__ c1Whh,
    const float* __restrict__ c1bih, const float* __restrict__ c1bhh,
    const float* __restrict__ c2Wih, const float* __restrict__ c2Whh,
    const float* __restrict__ c2bih, const float* __restrict__ c2bhh,
    float* __restrict__ out)
{
    __shared__ float s_x[16 * 516];
    __shared__ float s_g[256];
    __shared__ float s_h2[HH];
    __shared__ float s_pred[NN];
    __shared__ float s_ss[NN];
    unsigned* ctr = &g_barctr[2];
    unsigned tgt = NBLK;
    int tid = threadIdx.x;

    for (int h = 0; h < HZ; h++) {
        // phase A: pred + ARMA + xin (16 blocks, one per batch)
        if (blockIdx.x < BB) {
            int b = blockIdx.x;
            const float* h2 = g_dh2s[h];
            for (int i = tid; i < HH; i += 256) s_h2[i] = h2[b * HH + i];
            for (int i = tid; i < NN; i += 256) s_ss[i] = 0.f;
            __syncthreads();
            for (int n = tid; n < NN; n += 256) {
                const float* wr = Wp + (size_t)n * HH;
                float d0 = 0.f, d1 = 0.f, d2 = 0.f, d3 = 0.f;
#pragma unroll 8
                for (int k = 0; k < HH; k += 4) {
                    float4 wv = *reinterpret_cast<const float4*>(wr + k);
                    d0 += wv.x * s_h2[k]; d1 += wv.y * s_h2[k + 1];
                    d2 += wv.z * s_h2[k + 2]; d3 += wv.w * s_h2[k + 3];
                }
                float d = (d0 + d1) + (d2 + d3) + bp[n];
                s_pred[n] = d;
                out[(b * NN + n) * HZ + h] = d;
            }
            __syncthreads();
            for (int e = tid; e < EE; e += 256)
                atomicAdd(&s_ss[ei[EE + e]], g_norm[e] * s_pred[ei[e]]);
            __syncthreads();
            for (int idx = tid; idx < NC; idx += 256) {
                int n = idx >> 5, c = idx & 31;
                float val = geluf(s_ss[n] * gw[c] + s_pred[n] * gv[c] + gb[c]);
                g_dxins[h][(size_t)b * NC + idx] = val + emb[idx];
            }
        }
        gbar(ctr, tgt);
        // phase B: cell 1 (K = 3200)
        cellstep(g_dxins[h], NC, g_dh1s[h], g_dh1s[h + 1], g_dc1,
                 c1Wih, c1Whh, c1bih, c1bhh, s_x, s_g);
        gbar(ctr, tgt);
        // phase C: cell 2 (K = 512)
        cellstep(g_dh1s[h + 1], HH, g_dh2s[h], g_dh2s[h + 1], g_dc2,
                 c2Wih, c2Whh, c2bih, c2bhh, s_x, s_g);
        if (h < HZ - 1) gbar(ctr, tgt);
    }
}

// ------------------------- launch -------------------------
extern "C" void kernel_launch(void* const* d_in, const int* in_sizes, int n_in,
                              void* d_out, int out_size) {
    const float* window = (const float*)d_in[0];
    const int*   ei     = (const int*)d_in[1];
    const float* ew     = (const float*)d_in[2];
    const float* emb    = (const float*)d_in[3];
    const float* tg_w   = (const float*)d_in[4];
    const float* tg_v   = (const float*)d_in[5];
    const float* tg_b   = (const float*)d_in[6];
    const float* gnn_w  = (const float*)d_in[7];
    const float* gnn_v  = (const float*)d_in[8];
    const float* gnn_b  = (const float*)d_in[9];
    const float* Wih0   = (const float*)d_in[10];
    const float* Whh0   = (const float*)d_in[11];
    const float* bih0   = (const float*)d_in[12];
    const float* bhh0   = (const float*)d_in[13];
    const float* Wih1   = (const float*)d_in[14];
    const float* Whh1   = (const float*)d_in[15];
    const float* bih1   = (const float*)d_in[16];
    const float* bhh1   = (const float*)d_in[17];
    const float* c1Wih  = (const float*)d_in[18];
    const float* c1Whh  = (const float*)d_in[19];
    const float* c1bih  = (const float*)d_in[20];
    const float* c1bhh  = (const float*)d_in[21];
    const float* c2Wih  = (const float*)d_in[22];
    const float* c2Whh  = (const float*)d_in[23];
    const float* c2bih  = (const float*)d_in[24];
    const float* c2bhh  = (const float*)d_in[25];
    const float* Wp     = (const float*)d_in[26];
    const float* bp     = (const float*)d_in[27];
    float* out = (float*)d_out;

    const int REC_SMEM = (16 * 512 + 16 * 516 + 256) * 4;   // 66816 B
    cudaFuncSetAttribute(k_rec, cudaFuncAttributeMaxDynamicSharedMemorySize, REC_SMEM);

    k_zero<<<32, 256>>>();
    k_prep<<<1, 256>>>(ei, ew);
    k_tg<<<TB, 256>>>(window, ei, tg_w, tg_v, tg_b, emb);

    dim3 gg(G4 / 128, TB / 128);
    k_gemm_nt<<<gg, 256>>>(0, Wih0, bih0, bhh0);
    k_rec<<<NBLK, 256, REC_SMEM>>>(0, Whh0);
    k_gemm_nt<<<gg, 256>>>(1, Wih1, bih1, bhh1);
    k_rec<<<NBLK, 256, REC_SMEM>>>(1, Whh1);

    k_copyfin<<<32, 256>>>();
    k_dec<<<NBLK, 256>>>(Wp, bp, ei, gnn_w, gnn_v, gnn_b, emb,
                         c1Wih, c1Whh, c1bih, c1bhh,
                         c2Wih, c2Whh, c2bih, c2bhh, out);
    (void)in_sizes; (void)n_in; (void)out_size;
}

// round 5
// speedup vs baseline: 1.8092x; 1.0017x over previous
#include <cuda_runtime.h>
#include <math.h>

#define NN 100
#define CC 32
#define HH 512
#define TT 64
#define BB 16
#define EE 2000
#define HZ 10
#define NC 3200    // NN*CC
#define G4 2048    // 4*HH
#define TB 1024    // TT*BB
#define NBLK 128   // persistent grid size

// ------------------------- device scratch -------------------------
__device__ float g_norm[EE];
__device__ float g_Xin[TB * NC];
__device__ float g_G0[TB * G4];
__device__ float g_G1[TB * G4];
__device__ float g_hs0[(TT + 1) * BB * HH];   // slot 0 never written => zeros
__device__ float g_hs1[(TT + 1) * BB * HH];
__device__ float g_c0[BB * HH];
__device__ float g_c1l[BB * HH];
__device__ float g_dh1s[HZ + 1][BB * HH];
__device__ float g_dh2s[HZ + 1][BB * HH];
__device__ float g_dc1[BB * HH];
__device__ float g_dc2[BB * HH];
__device__ float g_dxins[HZ][BB * NC];
__device__ unsigned g_barctr[3];

__device__ __forceinline__ float geluf(float x) {
    return 0.5f * x * (1.0f + erff(x * 0.70710678118654752f));
}
__device__ __forceinline__ float sigmf(float x) { return 1.0f / (1.0f + expf(-x)); }

// grid barrier: all NBLK blocks co-resident (grid <= #SMs)
__device__ __forceinline__ void gbar(unsigned* ctr, unsigned& tgt) {
    __threadfence();
    __syncthreads();
    if (threadIdx.x == 0) {
        atomicAdd(ctr, 1u);
        while (*(volatile unsigned*)ctr < tgt) { }
    }
    __syncthreads();
    tgt += NBLK;
}

// ------------------------- init / prep -------------------------
__global__ void k_zero() {
    int i = blockIdx.x * blockDim.x + threadIdx.x;
    if (i < BB * HH) { g_c0[i] = 0.f; g_c1l[i] = 0.f; }
    if (i < 3) g_barctr[i] = 0u;
}

__global__ void k_prep(const int* __restrict__ ei, const float* __restrict__ ew) {
    __shared__ float sdeg[NN];
    __shared__ float sdinv[NN];
    int tid = threadIdx.x;
    for (int n = tid; n < NN; n += blockDim.x) sdeg[n] = 0.f;
    __syncthreads();
    for (int e = tid; e < EE; e += blockDim.x) atomicAdd(&sdeg[ei[EE + e]], ew[e]);
    __syncthreads();
    for (int n = tid; n < NN; n += blockDim.x) {
        float d = sdeg[n];
        sdinv[n] = (d > 0.f) ? rsqrtf(fmaxf(d, 1e-12f)) : 0.f;
    }
    __syncthreads();
    for (int e = tid; e < EE; e += blockDim.x)
        g_norm[e] = sdinv[ei[e]] * ew[e] * sdinv[ei[EE + e]];
}

// ------------------------- temporal ARMA + embed -------------------------
__global__ void k_tg(const float* __restrict__ win, const int* __restrict__ ei,
                     const float* __restrict__ tw, const float* __restrict__ tv,
                     const float* __restrict__ tb, const float* __restrict__ emb) {
    __shared__ float s[NN];
    int p = blockIdx.x;
    int base = (p >> 4) * (BB * NN) + (p & 15) * NN;
    int tid = threadIdx.x;
    for (int n = tid; n < NN; n += blockDim.x) s[n] = 0.f;
    __syncthreads();
    for (int e = tid; e < EE; e += blockDim.x)
        atomicAdd(&s[ei[EE + e]], g_norm[e] * win[base + ei[e]]);
    __syncthreads();
    for (int idx = tid; idx < NC; idx += blockDim.x) {
        int n = idx >> 5, c = idx & 31;
        float x = win[base + n];
        float val = geluf(s[n] * tw[c] + x * tv[c] + tb[c]);
        int j = base + n;
        int t2 = j & (TT - 1);
        int rest = j >> 6;
        int n2 = rest % NN, b2 = rest / NN;
        g_Xin[(size_t)(t2 * BB + b2) * NC + n2 * CC + c] = val + emb[n2 * CC + c];
    }
}

// ------------------------- NT SGEMM (M=1024, N=2048) -------------------------
__global__ void k_gemm_nt(int sel, const float* __restrict__ W,
                          const float* __restrict__ b1, const float* __restrict__ b2) {
    const float* A;
    float* Cc;
    int K;
    if (sel == 0) { A = g_Xin; Cc = g_G0; K = NC; }
    else          { A = g_hs0 + BB * HH; Cc = g_G1; K = HH; }

    __shared__ __align__(16) float As[16][128];
    __shared__ __align__(16) float Bs[16][128];
    int tid = threadIdx.x;
    int m0 = blockIdx.y * 128, n0 = blockIdx.x * 128;
    int tm = tid >> 4, tn = tid & 15;
    int li = tid >> 2, lj = (tid & 3) << 2;

    float acc[8][8];
#pragma unroll
    for (int i = 0; i < 8; i++)
#pragma unroll
        for (int j = 0; j < 8; j++) acc[i][j] = 0.f;

    for (int k0 = 0; k0 < K; k0 += 16) {
        float4 a0 = *reinterpret_cast<const float4*>(A + (size_t)(m0 + li) * K + k0 + lj);
        float4 a1 = *reinterpret_cast<const float4*>(A + (size_t)(m0 + li + 64) * K + k0 + lj);
        float4 w0 = *reinterpret_cast<const float4*>(W + (size_t)(n0 + li) * K + k0 + lj);
        float4 w1 = *reinterpret_cast<const float4*>(W + (size_t)(n0 + li + 64) * K + k0 + lj);
        __syncthreads();
        As[lj + 0][li] = a0.x; As[lj + 1][li] = a0.y; As[lj + 2][li] = a0.z; As[lj + 3][li] = a0.w;
        As[lj + 0][li + 64] = a1.x; As[lj + 1][li + 64] = a1.y; As[lj + 2][li + 64] = a1.z; As[lj + 3][li + 64] = a1.w;
        Bs[lj + 0][li] = w0.x; Bs[lj + 1][li] = w0.y; Bs[lj + 2][li] = w0.z; Bs[lj + 3][li] = w0.w;
        Bs[lj + 0][li + 64] = w1.x; Bs[lj + 1][li + 64] = w1.y; Bs[lj + 2][li + 64] = w1.z; Bs[lj + 3][li + 64] = w1.w;
        __syncthreads();
#pragma unroll
        for (int kk = 0; kk < 16; kk++) {
            float ra[8], rb[8];
            *reinterpret_cast<float4*>(&ra[0]) = *reinterpret_cast<float4*>(&As[kk][tm * 8]);
            *reinterpret_cast<float4*>(&ra[4]) = *reinterpret_cast<float4*>(&As[kk][tm * 8 + 4]);
            *reinterpret_cast<float4*>(&rb[0]) = *reinterpret_cast<float4*>(&Bs[kk][tn * 8]);
            *reinterpret_cast<float4*>(&rb[4]) = *reinterpret_cast<float4*>(&Bs[kk][tn * 8 + 4]);
#pragma unroll
            for (int i = 0; i < 8; i++)
#pragma unroll
                for (int j = 0; j < 8; j++) acc[i][j] += ra[i] * rb[j];
        }
    }

    float bias[8];
#pragma unroll
    for (int j = 0; j < 8; j++) bias[j] = b1[n0 + tn * 8 + j] + b2[n0 + tn * 8 + j];
#pragma unroll
    for (int i = 0; i < 8; i++) {
        float* cp = Cc + (size_t)(m0 + tm * 8 + i) * G4 + n0 + tn * 8;
#pragma unroll
        for (int j = 0; j < 8; j++) cp[j] = acc[i][j] + bias[j];
    }
}

// ------------------------- persistent recurrence (one layer, 64 steps) ------
// dyn smem: swhh[16*512] | sh[16*516] | sg[256]
extern __shared__ float dynsm[];

__global__ void __launch_bounds__(256) k_rec(int layer, const float* __restrict__ Whh) {
    float* swhh = dynsm;
    float* sh = dynsm + 16 * 512;
    float* sg = dynsm + 16 * 512 + 16 * 516;
    const float* Gall = (layer == 0) ? g_G0 : g_G1;
    float* hs = (layer == 0) ? g_hs0 : g_hs1;
    float* c_st = (layer == 0) ? g_c0 : g_c1l;
    unsigned* ctr = &g_barctr[layer];

    int tid = threadIdx.x;
    int rowid = tid >> 4, bb = tid & 15;
    int bq = tid >> 4, q = tid & 15;
    int row = (rowid >> 2) * HH + blockIdx.x * 4 + (rowid & 3);

    // cache the block's 16 Whh rows in smem (once for all 64 steps)
    for (int i = tid; i < 16 * 128; i += 256) {
        int r = i >> 7, k4 = (i & 127) << 2;
        int grow = (r >> 2) * HH + blockIdx.x * 4 + (r & 3);
        *reinterpret_cast<float4*>(swhh + r * 512 + k4) =
            *reinterpret_cast<const float4*>(Whh + (size_t)grow * HH + k4);
    }

    unsigned tgt = NBLK;
    for (int t = 0; t < TT; t++) {
        const float* h_in = hs + (size_t)t * BB * HH;
        __syncthreads();
#pragma unroll
        for (int m = 0; m < 8; m++) {
            float4 v = *reinterpret_cast<const float4*>(h_in + bq * HH + m * 64 + q * 4);
            *reinterpret_cast<float4*>(sh + bq * 516 + m * 64 + q * 4) = v;
        }
        __syncthreads();
        const float* w = swhh + rowid * 512;
        const float* hr = sh + bb * 516;
        float a0 = 0.f, a1 = 0.f, a2 = 0.f, a3 = 0.f;
#pragma unroll 16
        for (int k = 0; k < HH; k += 4) {
            float4 wv = *reinterpret_cast<const float4*>(w + k);
            float4 hv = *reinterpret_cast<const float4*>(hr + k);
            a0 += wv.x * hv.x; a1 += wv.y * hv.y; a2 += wv.z * hv.z; a3 += wv.w * hv.w;
        }
        sg[rowid * 16 + bb] = (a0 + a1) + (a2 + a3) +
                              Gall[(size_t)t * BB * G4 + bb * G4 + row];
        __syncthreads();
        if (tid < 64) {
            int jq = tid >> 4, b = tid & 15;
            float iv = sigmf(sg[jq * 16 + b]);
            float fv = sigmf(sg[(4 + jq) * 16 + b]);
            float gv = tanhf(sg[(8 + jq) * 16 + b]);
            float ov = sigmf(sg[(12 + jq) * 16 + b]);
            int idx = b * HH + blockIdx.x * 4 + jq;
            float cn = fv * c_st[idx] + iv * gv;
            c_st[idx] = cn;
            hs[(size_t)(t + 1) * BB * HH + idx] = ov * tanhf(cn);
        }
        if (t < TT - 1) gbar(ctr, tgt);
    }
}

// ------------------------- decoder state seed -------------------------
__global__ void k_copyfin() {
    int i = blockIdx.x * blockDim.x + threadIdx.x;
    if (i < BB * HH) {
        float v0 = g_hs0[(size_t)TT * BB * HH + i];
        g_dh1s[0][i] = v0; g_dc1[i] = v0;
        float v1 = g_hs1[(size_t)TT * BB * HH + i];
        g_dh2s[0][i] = v1; g_dc2[i] = v1;
    }
}

// ------------------------- decoder LSTM cell (device) -------------------------
__device__ __forceinline__ void cellstep(
    const float* __restrict__ x, int Kx,
    const float* __restrict__ h_in, float* __restrict__ h_out,
    float* __restrict__ c_st,
    const float* __restrict__ Wih, const float* __restrict__ Whh,
    const float* __restrict__ bih, const float* __restrict__ bhh,
    float* s_x, float* s_g)
{
    int tid = threadIdx.x;
    int rowid = tid >> 4, bb = tid & 15;
    int bq = tid >> 4, q = tid & 15;
    int row = (rowid >> 2) * HH + blockIdx.x * 4 + (rowid & 3);
    float a0 = 0.f, a1 = 0.f, a2 = 0.f, a3 = 0.f;

    for (int k0 = 0; k0 < Kx; k0 += 512) {
        int len = min(512, Kx - k0);
        __syncthreads();
        for (int m = 0; m * 64 < len; m++) {
            float4 v = *reinterpret_cast<const float4*>(x + (size_t)bq * Kx + k0 + m * 64 + q * 4);
            *reinterpret_cast<float4*>(s_x + bq * 516 + m * 64 + q * 4) = v;
        }
        __syncthreads();
        const float* w = Wih + (size_t)row * Kx + k0;
        const float* hr = s_x + bb * 516;
#pragma unroll 8
        for (int k = 0; k < len; k += 4) {
            float4 wv = *reinterpret_cast<const float4*>(w + k);
            float4 hv = *reinterpret_cast<const float4*>(hr + k);
            a0 += wv.x * hv.x; a1 += wv.y * hv.y; a2 += wv.z * hv.z; a3 += wv.w * hv.w;
        }
    }

    __syncthreads();
#pragma unroll
    for (int m = 0; m < 8; m++) {
        float4 v = *reinterpret_cast<const float4*>(h_in + bq * HH + m * 64 + q * 4);
        *reinterpret_cast<float4*>(s_x + bq * 516 + m * 64 + q * 4) = v;
    }
    __syncthreads();
    {
        const float* w = Whh + (size_t)row * HH;
        const float* hr = s_x + bb * 516;
#pragma unroll 8
        for (int k = 0; k < HH; k += 4) {
            float4 wv = *reinterpret_cast<const float4*>(w + k);
            float4 hv = *reinterpret_cast<const float4*>(hr + k);
            a0 += wv.x * hv.x; a1 += wv.y * hv.y; a2 += wv.z * hv.z; a3 += wv.w * hv.w;
        }
    }
    s_g[rowid * 16 + bb] = (a0 + a1) + (a2 + a3) + bih[row] + bhh[row];
    __syncthreads();
    if (tid < 64) {
        int jq = tid >> 4, b = tid & 15;
        float iv = sigmf(s_g[jq * 16 + b]);
        float fv = sigmf(s_g[(4 + jq) * 16 + b]);
        float gv = tanhf(s_g[(8 + jq) * 16 + b]);
        float ov = sigmf(s_g[(12 + jq) * 16 + b]);
        int idx = b * HH + blockIdx.x * 4 + jq;
        float cn = fv * c_st[idx] + iv * gv;
        c_st[idx] = cn;
        h_out[idx] = ov * tanhf(cn);
    }
}

// ------------------------- persistent decoder (all 10 horizon steps) --------
__global__ void __launch_bounds__(256) k_dec(
    const float* __restrict__ Wp, const float* __restrict__ bp,
    const int* __restrict__ ei,
    const float* __restrict__ gw, const float* __restrict__ gv,
    const float* __restrict__ gb, const float* __restrict__ emb,
    const float* __restrict__ c1Wih, const float* __restrict__ c1Whh,
    const float* __restrict__ c1bih, const float* __restrict__ c1bhh,
    const float* __restrict__ c2Wih, const float* __restrict__ c2Whh,
    const float* __restrict__ c2bih, const float* __restrict__ c2bhh,
    float* __restrict__ out)
{
    __shared__ float s_x[16 * 516];
    __shared__ float s_g[256];
    __shared__ float s_h2[HH];
    __shared__ float s_pred[NN];
    __shared__ float s_ss[NN];
    unsigned* ctr = &g_barctr[2];
    unsigned tgt = NBLK;
    int tid = threadIdx.x;

    for (int h = 0; h < HZ; h++) {
        // phase A: pred + ARMA + xin (16 blocks, one per batch)
        if (blockIdx.x < BB) {
            int b = blockIdx.x;
            const float* h2 = g_dh2s[h];
            for (int i = tid; i < HH; i += 256) s_h2[i] = h2[b * HH + i];
            for (int i = tid; i < NN; i += 256) s_ss[i] = 0.f;
            __syncthreads();
            for (int n = tid; n < NN; n += 256) {
                const float* wr = Wp + (size_t)n * HH;
                float d0 = 0.f, d1 = 0.f, d2 = 0.f, d3 = 0.f;
#pragma unroll 8
                for (int k = 0; k < HH; k += 4) {
                    float4 wv = *reinterpret_cast<const float4*>(wr + k);
                    d0 += wv.x * s_h2[k]; d1 += wv.y * s_h2[k + 1];
                    d2 += wv.z * s_h2[k + 2]; d3 += wv.w * s_h2[k + 3];
                }
                float d = (d0 + d1) + (d2 + d3) + bp[n];
                s_pred[n] = d;
                out[(b * NN + n) * HZ + h] = d;
            }
            __syncthreads();
            for (int e = tid; e < EE; e += 256)
                atomicAdd(&s_ss[ei[EE + e]], g_norm[e] * s_pred[ei[e]]);
            __syncthreads();
            for (int idx = tid; idx < NC; idx += 256) {
                int n = idx >> 5, c = idx & 31;
                float val = geluf(s_ss[n] * gw[c] + s_pred[n] * gv[c] + gb[c]);
                g_dxins[h][(size_t)b * NC + idx] = val + emb[idx];
            }
        }
        gbar(ctr, tgt);
        // phase B: cell 1 (K = 3200)
        cellstep(g_dxins[h], NC, g_dh1s[h], g_dh1s[h + 1], g_dc1,
                 c1Wih, c1Whh, c1bih, c1bhh, s_x, s_g);
        gbar(ctr, tgt);
        // phase C: cell 2 (K = 512)
        cellstep(g_dh1s[h + 1], HH, g_dh2s[h], g_dh2s[h + 1], g_dc2,
                 c2Wih, c2Whh, c2bih, c2bhh, s_x, s_g);
        if (h < HZ - 1) gbar(ctr, tgt);
    }
}

// ------------------------- launch -------------------------
extern "C" void kernel_launch(void* const* d_in, const int* in_sizes, int n_in,
                              void* d_out, int out_size) {
    const float* window = (const float*)d_in[0];
    const int*   ei     = (const int*)d_in[1];
    const float* ew     = (const float*)d_in[2];
    const float* emb    = (const float*)d_in[3];
    const float* tg_w   = (const float*)d_in[4];
    const float* tg_v   = (const float*)d_in[5];
    const float* tg_b   = (const float*)d_in[6];
    const float* gnn_w  = (const float*)d_in[7];
    const float* gnn_v  = (const float*)d_in[8];
    const float* gnn_b  = (const float*)d_in[9];
    const float* Wih0   = (const float*)d_in[10];
    const float* Whh0   = (const float*)d_in[11];
    const float* bih0   = (const float*)d_in[12];
    const float* bhh0   = (const float*)d_in[13];
    const float* Wih1   = (const float*)d_in[14];
    const float* Whh1   = (const float*)d_in[15];
    const float* bih1   = (const float*)d_in[16];
    const float* bhh1   = (const float*)d_in[17];
    const float* c1Wih  = (const float*)d_in[18];
    const float* c1Whh  = (const float*)d_in[19];
    const float* c1bih  = (const float*)d_in[20];
    const float* c1bhh  = (const float*)d_in[21];
    const float* c2Wih  = (const float*)d_in[22];
    const float* c2Whh  = (const float*)d_in[23];
    const float* c2bih  = (const float*)d_in[24];
    const float* c2bhh  = (const float*)d_in[25];
    const float* Wp     = (const float*)d_in[26];
    const float* bp     = (const float*)d_in[27];
    float* out = (float*)d_out;

    const int REC_SMEM = (16 * 512 + 16 * 516 + 256) * 4;   // 66816 B
    cudaFuncSetAttribute(k_rec, cudaFuncAttributeMaxDynamicSharedMemorySize, REC_SMEM);

    k_zero<<<32, 256>>>();
    k_prep<<<1, 256>>>(ei, ew);
    k_tg<<<TB, 256>>>(window, ei, tg_w, tg_v, tg_b, emb);

    dim3 gg(G4 / 128, TB / 128);
    k_gemm_nt<<<gg, 256>>>(0, Wih0, bih0, bhh0);
    k_rec<<<NBLK, 256, REC_SMEM>>>(0, Whh0);
    k_gemm_nt<<<gg, 256>>>(1, Wih1, bih1, bhh1);
    k_rec<<<NBLK, 256, REC_SMEM>>>(1, Whh1);

    k_copyfin<<<32, 256>>>();
    k_dec<<<NBLK, 256>>>(Wp, bp, ei, gnn_w, gnn_v, gnn_b, emb,
                         c1Wih, c1Whh, c1bih, c1bhh,
                         c2Wih, c2Whh, c2bih, c2bhh, out);
    (void)in_sizes; (void)n_in; (void)out_size;
}